// round 2
// baseline (speedup 1.0000x reference)
#include <cuda_runtime.h>
#include <cstdint>

// Problem shapes (fixed by the dataset)
#define B_   256
#define CIN  128
#define NPTS 1024
#define M_   1023
#define COUT 64
#define M3   3069      // 3*M
#define OUTW 1024      // M+1 output columns

// Scratch (allocation-free rule: __device__ globals)
__device__ float g_treesT[(size_t)B_ * NPTS * CIN];   // [b][n][c]  (c contiguous)
__device__ float g_Wt[3 * CIN * COUT];                // [k][c][o]  (o contiguous)
__device__ int   g_idx_is64;                          // 1 if indexes buffer is int64

// ---------------------------------------------------------------------------
// Packed fp32x2 helpers (Blackwell sm_100a)
// ---------------------------------------------------------------------------
#define PACK2(d, f) \
    asm("mov.b64 %0, {%1, %1};" : "=l"(d) : "r"(__float_as_uint(f)))
#define FFMA2(d, a, b) \
    asm("fma.rn.f32x2 %0, %1, %2, %0;" : "+l"(d) : "l"(a), "l"(b))

// ---------------------------------------------------------------------------
// Kernel 0: detect index dtype. If the buffer is int64 (values < 1024), every
// odd int32 word is zero. Sampling 1024 odd words: all-zero => int64.
// Reads int32 positions 2i+1 < 2048 — in bounds for both interpretations.
// ---------------------------------------------------------------------------
__global__ void detect_kernel(const int* __restrict__ idx32) {
    __shared__ int any_nonzero;
    if (threadIdx.x == 0) any_nonzero = 0;
    __syncthreads();
    int nz = 0;
    for (int i = threadIdx.x; i < 1024; i += blockDim.x)
        nz |= (idx32[2 * i + 1] != 0);
    if (nz) atomicOr(&any_nonzero, 1);
    __syncthreads();
    if (threadIdx.x == 0) g_idx_is64 = any_nonzero ? 0 : 1;
}

// ---------------------------------------------------------------------------
// Kernel 1: transpose trees[b][c][n] -> treesT[b][n][c]
// grid (NPTS/32, CIN/32, B), block (32, 8)
// ---------------------------------------------------------------------------
__global__ void transpose_kernel(const float* __restrict__ trees) {
    __shared__ float tile[32][33];
    int b = blockIdx.z;
    int nBase = blockIdx.x * 32;
    int cBase = blockIdx.y * 32;
    int tx = threadIdx.x, ty = threadIdx.y;
    const float* src = trees + (size_t)b * CIN * NPTS;
    float* dst = g_treesT + (size_t)b * NPTS * CIN;
    #pragma unroll
    for (int i = 0; i < 4; i++)
        tile[ty + 8 * i][tx] = src[(size_t)(cBase + ty + 8 * i) * NPTS + nBase + tx];
    __syncthreads();
    #pragma unroll
    for (int i = 0; i < 4; i++)
        dst[(size_t)(nBase + ty + 8 * i) * CIN + cBase + tx] = tile[tx][ty + 8 * i];
}

// ---------------------------------------------------------------------------
// Kernel 2: restage W[o][c][k] -> Wt[k][c][o]
// ---------------------------------------------------------------------------
__global__ void wprep_kernel(const float* __restrict__ W) {
    int i = blockIdx.x * 256 + threadIdx.x;
    if (i < 3 * CIN * COUT) {
        int o = i % COUT;
        int c = (i / COUT) % CIN;
        int k = i / (COUT * CIN);
        g_Wt[i] = W[(o * CIN + c) * 3 + k];
    }
}

// ---------------------------------------------------------------------------
// Kernel 3: the gather-GEMM
// grid (8, 256): blockIdx.x = m-tile of 128, blockIdx.y = batch. 128 threads.
// Block tile: 64 o x 128 m. K = 384 split as (k in 0..2) x (c chunks of 16).
// Thread tile: 8 o x 8 m via fma.rn.f32x2 (4 m-pairs).
// ---------------------------------------------------------------------------
#define TM 128
#define KC 16
#define NCHUNK 24   // 3 * (128/16)

__global__ void __launch_bounds__(128, 3) convtree_kernel(
    const void* __restrict__ indexes_raw,
    const float* __restrict__ bias,
    float* __restrict__ out)
{
    __shared__ int sidx[TM * 3];
    __shared__ float bsm[COUT];
    __shared__ __align__(16) float Ws[2][KC][COUT];
    __shared__ __align__(16) float Gs[2][KC][TM];
    __shared__ float stage[COUT][65];

    const int b   = blockIdx.y;
    const int m0  = blockIdx.x * TM;
    const int tid = threadIdx.x;
    const int is64 = g_idx_is64;

    // Load gather indices for this m-tile, guard m >= M_, clamp to [0,1023]
    const int* i32 = (const int*)indexes_raw;
    const long long* i64 = (const long long*)indexes_raw;
    for (int e = tid; e < TM * 3; e += 128) {
        int gm = m0 + e / 3;
        int flat = b * M3 + 3 * gm + (e % 3);
        int v = 0;
        if (gm < M_) v = is64 ? (int)i64[flat] : i32[flat];
        sidx[e] = v & (NPTS - 1);
    }
    if (tid < COUT) bsm[tid] = bias[tid];

    const float* tb = g_treesT + (size_t)b * NPTS * CIN;

    const int og  = tid & 7;       // o-group 0..7
    const int mg  = tid >> 3;      // m-group 0..15
    const int o0  = og * 8;
    const int mg0 = mg * 8;

    unsigned long long acc[8][4];
    #pragma unroll
    for (int i = 0; i < 8; i++)
        #pragma unroll
        for (int j = 0; j < 4; j++) acc[i][j] = 0ull;

    __syncthreads();   // sidx visible

    // ---- prologue: chunk 0 (k=0, c0=0) into buffer 0 ----
    {
        const float4* wsrc = (const float4*)g_Wt;
        ((float4*)&Ws[0][0][0])[tid]       = wsrc[tid];
        ((float4*)&Ws[0][0][0])[tid + 128] = wsrc[tid + 128];
        int n = sidx[tid * 3 + 0];
        const float4* gsrc = (const float4*)(tb + (size_t)n * CIN);
        #pragma unroll
        for (int q4 = 0; q4 < 4; q4++) {
            float4 v = gsrc[q4];
            Gs[0][q4 * 4 + 0][tid] = v.x;
            Gs[0][q4 * 4 + 1][tid] = v.y;
            Gs[0][q4 * 4 + 2][tid] = v.z;
            Gs[0][q4 * 4 + 3][tid] = v.w;
        }
    }
    __syncthreads();

    int buf = 0;
    for (int q = 0; q < NCHUNK; q++) {
        const int nb = buf ^ 1;
        const bool pf = (q < NCHUNK - 1);

        // -- prefetch next chunk into registers (hide LDG behind compute) --
        float4 wp0, wp1, gp0, gp1, gp2, gp3;
        if (pf) {
            int q1 = q + 1;
            int kq = q1 >> 3;
            int c0 = (q1 & 7) * KC;
            const float4* wsrc = (const float4*)(g_Wt + (kq * CIN + c0) * COUT);
            wp0 = wsrc[tid];
            wp1 = wsrc[tid + 128];
            int n = sidx[tid * 3 + kq];
            const float4* gsrc = (const float4*)(tb + (size_t)n * CIN + c0);
            gp0 = gsrc[0]; gp1 = gsrc[1]; gp2 = gsrc[2]; gp3 = gsrc[3];
        }

        // -- compute current chunk --
        #pragma unroll
        for (int cc = 0; cc < KC; cc++) {
            float4 wa = *(const float4*)&Ws[buf][cc][o0];
            float4 wb = *(const float4*)&Ws[buf][cc][o0 + 4];
            ulonglong2 ga = *(const ulonglong2*)&Gs[buf][cc][mg0];
            ulonglong2 gb = *(const ulonglong2*)&Gs[buf][cc][mg0 + 4];
            unsigned long long wd[8];
            PACK2(wd[0], wa.x); PACK2(wd[1], wa.y);
            PACK2(wd[2], wa.z); PACK2(wd[3], wa.w);
            PACK2(wd[4], wb.x); PACK2(wd[5], wb.y);
            PACK2(wd[6], wb.z); PACK2(wd[7], wb.w);
            #pragma unroll
            for (int i = 0; i < 8; i++) {
                FFMA2(acc[i][0], wd[i], ga.x);
                FFMA2(acc[i][1], wd[i], ga.y);
                FFMA2(acc[i][2], wd[i], gb.x);
                FFMA2(acc[i][3], wd[i], gb.y);
            }
        }

        // -- commit prefetched regs to the other buffer --
        if (pf) {
            ((float4*)&Ws[nb][0][0])[tid]       = wp0;
            ((float4*)&Ws[nb][0][0])[tid + 128] = wp1;
            Gs[nb][ 0][tid] = gp0.x; Gs[nb][ 1][tid] = gp0.y;
            Gs[nb][ 2][tid] = gp0.z; Gs[nb][ 3][tid] = gp0.w;
            Gs[nb][ 4][tid] = gp1.x; Gs[nb][ 5][tid] = gp1.y;
            Gs[nb][ 6][tid] = gp1.z; Gs[nb][ 7][tid] = gp1.w;
            Gs[nb][ 8][tid] = gp2.x; Gs[nb][ 9][tid] = gp2.y;
            Gs[nb][10][tid] = gp2.z; Gs[nb][11][tid] = gp2.w;
            Gs[nb][12][tid] = gp3.x; Gs[nb][13][tid] = gp3.y;
            Gs[nb][14][tid] = gp3.z; Gs[nb][15][tid] = gp3.w;
        }
        __syncthreads();
        buf = nb;
    }

    // ---- epilogue: bias add, stage to smem, coalesced global store ----
    for (int h = 0; h < 2; h++) {
        __syncthreads();
        if ((mg0 >> 6) == h) {
            int cbase = mg0 & 63;
            #pragma unroll
            for (int i = 0; i < 8; i++) {
                float bo = bsm[o0 + i];
                #pragma unroll
                for (int j = 0; j < 4; j++) {
                    unsigned long long u = acc[i][j];
                    float lo = __uint_as_float((unsigned)(u & 0xffffffffu));
                    float hi = __uint_as_float((unsigned)(u >> 32));
                    stage[o0 + i][cbase + 2 * j]     = lo + bo;
                    stage[o0 + i][cbase + 2 * j + 1] = hi + bo;
                }
            }
        }
        __syncthreads();
        int mbase = m0 + h * 64;
        for (int e = tid; e < COUT * 64; e += 128) {
            int o = e >> 6, col = e & 63;
            int gm = mbase + col;
            if (gm < M_)
                out[(size_t)(b * COUT + o) * OUTW + 1 + gm] = stage[o][col];
        }
    }
}

// ---------------------------------------------------------------------------
// Kernel 4: zero column m=0 everywhere; pass through indexes per out_size mode
// mode 0: results only; mode 1: indexes cast to float tail; mode 2: raw 8B tail
// ---------------------------------------------------------------------------
__global__ void tail_kernel(const void* __restrict__ idx_raw,
                            float* __restrict__ out, int mode) {
    int i = blockIdx.x * 256 + threadIdx.x;
    const int is64 = g_idx_is64;
    const int* i32 = (const int*)idx_raw;
    const long long* i64 = (const long long*)idx_raw;
    if (i < B_ * COUT) out[(size_t)i * OUTW] = 0.0f;
    if (i < B_ * M3) {
        long long v = is64 ? i64[i] : (long long)i32[i];
        if (mode == 1) {
            out[(size_t)B_ * COUT * OUTW + i] = (float)v;
        } else if (mode == 2) {
            ((long long*)out)[(size_t)(B_ * COUT * OUTW) / 2 + i] = v;
        }
    }
}

// ---------------------------------------------------------------------------
extern "C" void kernel_launch(void* const* d_in, const int* in_sizes, int n_in,
                              void* d_out, int out_size) {
    // Identify inputs by element count (robust to metadata ordering)
    const float* trees   = nullptr;
    const void*  indexes = nullptr;
    const float* W       = nullptr;
    const float* bias    = nullptr;
    for (int i = 0; i < n_in; i++) {
        switch (in_sizes[i]) {
            case B_ * CIN * NPTS: trees   = (const float*)d_in[i]; break;   // 33,554,432
            case B_ * M3:         indexes = d_in[i];               break;   // 785,664
            case COUT * CIN * 3:  W       = (const float*)d_in[i]; break;   // 24,576
            case COUT:            bias    = (const float*)d_in[i]; break;   // 64
        }
    }
    float* out = (float*)d_out;

    detect_kernel<<<1, 256>>>((const int*)indexes);
    transpose_kernel<<<dim3(NPTS / 32, CIN / 32, B_), dim3(32, 8)>>>(trees);
    wprep_kernel<<<(3 * CIN * COUT + 255) / 256, 256>>>(W);
    convtree_kernel<<<dim3(8, B_), 128>>>(indexes, bias, out);

    long long R = (long long)B_ * COUT * OUTW;          // 16,777,216
    long long I = (long long)B_ * M3;                   // 785,664
    int mode = 0;
    if ((long long)out_size >= R + 2 * I)      mode = 2;
    else if ((long long)out_size >= R + I)     mode = 1;
    tail_kernel<<<(B_ * M3 + 255) / 256, 256>>>(indexes, out, mode);
}

// round 4
// speedup vs baseline: 1.5039x; 1.5039x over previous
#include <cuda_runtime.h>
#include <cuda_bf16.h>
#include <cstdint>

#define B_   256
#define CIN  128
#define NPTS 1024
#define M_   1023
#define COUT 64
#define M3   3069
#define OUTW 1024

// ---------------- scratch (__device__ globals; no runtime alloc) ----------
__device__ __nv_bfloat16 g_thi[(size_t)B_ * NPTS * CIN];  // [b][n][c] hi
__device__ __nv_bfloat16 g_tlo[(size_t)B_ * NPTS * CIN];  // [b][n][c] lo
// W image, exactly the smem layout: [tap][mat][o row 256B, swizzled]
__device__ __align__(256) unsigned char g_Wsw[3 * 2 * 16384];
__device__ int g_idx_is64;

// ---------------- PTX helpers --------------------------------------------
__device__ __forceinline__ uint32_t smem_u32(const void* p) {
    uint32_t a;
    asm("{ .reg .u64 t; cvta.to.shared.u64 t, %1; cvt.u32.u64 %0, t; }"
        : "=r"(a) : "l"(p));
    return a;
}
#define CP_ASYNC16(dst, src) \
    asm volatile("cp.async.cg.shared.global [%0], [%1], 16;" :: "r"(dst), "l"(src) : "memory")
#define CP_COMMIT() asm volatile("cp.async.commit_group;" ::: "memory")
#define CP_WAIT0()  asm volatile("cp.async.wait_group 0;" ::: "memory")
#define CP_WAIT1()  asm volatile("cp.async.wait_group 1;" ::: "memory")

#define LDSM_X4(r0, r1, r2, r3, addr) \
    asm volatile("ldmatrix.sync.aligned.m8n8.x4.shared.b16 {%0,%1,%2,%3}, [%4];" \
        : "=r"(r0), "=r"(r1), "=r"(r2), "=r"(r3) : "r"(addr))

#define MMA_BF16(d, a, b0, b1) \
    asm volatile("mma.sync.aligned.m16n8k16.row.col.f32.bf16.bf16.f32 " \
        "{%0,%1,%2,%3}, {%4,%5,%6,%7}, {%8,%9}, {%0,%1,%2,%3};" \
        : "+f"((d)[0]), "+f"((d)[1]), "+f"((d)[2]), "+f"((d)[3]) \
        : "r"((a)[0]), "r"((a)[1]), "r"((a)[2]), "r"((a)[3]), "r"(b0), "r"(b1))

// ---------------- kernel 0: index dtype detection ------------------------
__global__ void detect_kernel(const int* __restrict__ idx32) {
    __shared__ int any_nz;
    if (threadIdx.x == 0) any_nz = 0;
    __syncthreads();
    int nz = 0;
    for (int i = threadIdx.x; i < 1024; i += blockDim.x)
        nz |= (idx32[2 * i + 1] != 0);
    if (nz) atomicOr(&any_nz, 1);
    __syncthreads();
    if (threadIdx.x == 0) g_idx_is64 = any_nz ? 0 : 1;
}

// ---------------- kernel 1: transpose + bf16 split -----------------------
__global__ void transpose_split_kernel(const float* __restrict__ trees) {
    __shared__ float tile[32][33];
    int b = blockIdx.z;
    int nBase = blockIdx.x * 32;
    int cBase = blockIdx.y * 32;
    int tx = threadIdx.x, ty = threadIdx.y;
    const float* src = trees + (size_t)b * CIN * NPTS;
    #pragma unroll
    for (int i = 0; i < 4; i++)
        tile[ty + 8 * i][tx] = src[(size_t)(cBase + ty + 8 * i) * NPTS + nBase + tx];
    __syncthreads();
    #pragma unroll
    for (int i = 0; i < 4; i++) {
        int n = nBase + ty + 8 * i;
        float v = tile[tx][ty + 8 * i];
        __nv_bfloat16 h = __float2bfloat16(v);
        __nv_bfloat16 l = __float2bfloat16(v - __bfloat162float(h));
        size_t off = (size_t)(b * NPTS + n) * CIN + cBase + tx;
        g_thi[off] = h;
        g_tlo[off] = l;
    }
}

// ---------------- kernel 2: W -> split + swizzled image ------------------
// image byte layout: tap*32768 + mat*16384 + o*256 + swz(g,o)*16 + (c&7)*2
// where g = c>>3, swz = (g&8) | ((g&7) ^ (o&7))
__global__ void wprep_kernel(const float* __restrict__ W) {
    int i = blockIdx.x * 256 + threadIdx.x;
    if (i >= 3 * 64 * 128) return;
    int c = i & 127;
    int o = (i >> 7) & 63;
    int k = i >> 13;
    float v = W[(o * CIN + c) * 3 + k];
    __nv_bfloat16 h = __float2bfloat16(v);
    __nv_bfloat16 l = __float2bfloat16(v - __bfloat162float(h));
    int g = c >> 3;
    uint32_t swz = (g & 8) | ((g & 7) ^ (o & 7));
    uint32_t off = k * 32768 + o * 256 + (swz << 4) + (c & 7) * 2;
    *(__nv_bfloat16*)(g_Wsw + off) = h;            // mat 0 (hi)
    *(__nv_bfloat16*)(g_Wsw + off + 16384) = l;    // mat 1 (lo)
}

// ---------------- kernel 3: gather + HMMA bf16 split GEMM ----------------
// grid (8, 256), 256 threads. Block tile: 128 m x 64 o, one batch.
// smem: sidx[384] | bias | W image (96KB) | A double buffer (2 x 64KB)
#define SM_SIDX  0
#define SM_BIAS  1536
#define SM_W     2048
#define SM_A     100352
#define SMEM_TOTAL 231424

__global__ void __launch_bounds__(256, 1) convtree_mma_kernel(
    const void* __restrict__ indexes_raw,
    const float* __restrict__ bias,
    float* __restrict__ out)
{
    extern __shared__ char smem[];
    const uint32_t sb = smem_u32(smem);
    const int tid  = threadIdx.x;
    const int lane = tid & 31;
    const int w    = tid >> 5;          // warp 0..7 -> m rows w*16..w*16+15
    const int b    = blockIdx.y;
    const int m0   = blockIdx.x * 128;

    int* sidx = (int*)(smem + SM_SIDX);
    float* bsm = (float*)(smem + SM_BIAS);

    // ---- indices + bias ----
    {
        const int is64 = g_idx_is64;
        const int* i32 = (const int*)indexes_raw;
        const long long* i64 = (const long long*)indexes_raw;
        for (int e = tid; e < 384; e += 256) {
            int gm = m0 + e / 3;
            int v = 0;
            if (gm < M_) {
                int flat = b * M3 + 3 * gm + (e % 3);
                v = is64 ? (int)i64[flat] : i32[flat];
            }
            sidx[e] = v & (NPTS - 1);
        }
        if (tid < COUT) bsm[tid] = bias[tid];
    }
    __syncthreads();

    const int mat = tid >> 7;           // 0 = hi, 1 = lo (for gather staging)
    const int mrow = tid & 127;
    const __nv_bfloat16* tbase = (mat ? g_tlo : g_thi) + (size_t)b * NPTS * CIN;

    // ---- prologue: W image (linear, pre-swizzled) + tap 0 gather ----
    for (int i = tid; i < 6144; i += 256)
        CP_ASYNC16(sb + SM_W + i * 16, (const char*)g_Wsw + i * 16);
    {
        const __nv_bfloat16* src = tbase + (size_t)sidx[mrow * 3 + 0] * CIN;
        uint32_t dbase = sb + SM_A + mat * 32768 + mrow * 256;
        #pragma unroll
        for (int g = 0; g < 16; g++) {
            uint32_t swz = (g & 8) | ((g & 7) ^ (mrow & 7));
            CP_ASYNC16(dbase + (swz << 4), (const char*)src + g * 16);
        }
    }
    CP_COMMIT();

    float acc[8][4];
    #pragma unroll
    for (int nt = 0; nt < 8; nt++)
        #pragma unroll
        for (int j = 0; j < 4; j++) acc[nt][j] = 0.0f;

    // lane-derived ldmatrix source coordinates
    const int a_row  = w * 16 + (lane & 15);
    const int a_gsel = lane >> 4;                       // 0/1
    const int b_row  = ((lane >> 4) << 3) + (lane & 7); // 0..15 within nt-pair
    const int b_gsel = (lane >> 3) & 1;

    int buf = 0;
    for (int tap = 0; tap < 3; tap++) {
        if (tap < 2) {  // prefetch next tap into other buffer
            const __nv_bfloat16* src = tbase + (size_t)sidx[mrow * 3 + tap + 1] * CIN;
            uint32_t dbase = sb + SM_A + (buf ^ 1) * 65536 + mat * 32768 + mrow * 256;
            #pragma unroll
            for (int g = 0; g < 16; g++) {
                uint32_t swz = (g & 8) | ((g & 7) ^ (mrow & 7));
                CP_ASYNC16(dbase + (swz << 4), (const char*)src + g * 16);
            }
            CP_COMMIT();
            CP_WAIT1();
        } else {
            CP_WAIT0();
        }
        __syncthreads();   // staged data visible to all warps

        const uint32_t abase = sb + SM_A + buf * 65536 + a_row * 256;
        const uint32_t wtap  = sb + SM_W + tap * 32768;

        #pragma unroll
        for (int ks = 0; ks < 8; ks++) {
            const int g0 = ks * 2;
            // A fragments (hi, lo)
            uint32_t ah[4], al[4];
            {
                int ga = g0 + a_gsel;
                uint32_t swz = (ga & 8) | ((ga & 7) ^ (a_row & 7));
                uint32_t addr = abase + (swz << 4);
                LDSM_X4(ah[0], ah[1], ah[2], ah[3], addr);
                LDSM_X4(al[0], al[1], al[2], al[3], addr + 32768);
            }
            // B fragments per n-tile pair, hi and lo
            #pragma unroll
            for (int ntp = 0; ntp < 4; ntp++) {
                int brow = ntp * 16 + b_row;
                int gb = g0 + b_gsel;
                uint32_t swz = (gb & 8) | ((gb & 7) ^ (brow & 7));
                uint32_t waddr = wtap + brow * 256 + (swz << 4);
                uint32_t bh[4], bl[4];
                LDSM_X4(bh[0], bh[1], bh[2], bh[3], waddr);
                LDSM_X4(bl[0], bl[1], bl[2], bl[3], waddr + 16384);
                MMA_BF16(acc[2 * ntp],     ah, bh[0], bh[1]);
                MMA_BF16(acc[2 * ntp],     al, bh[0], bh[1]);
                MMA_BF16(acc[2 * ntp],     ah, bl[0], bl[1]);
                MMA_BF16(acc[2 * ntp + 1], ah, bh[2], bh[3]);
                MMA_BF16(acc[2 * ntp + 1], al, bh[2], bh[3]);
                MMA_BF16(acc[2 * ntp + 1], ah, bl[2], bl[3]);
            }
        }
        __syncthreads();   // all warps done reading buf before it is refilled
        buf ^= 1;
    }

    // ---- epilogue: regs -> smem transpose (reuse A region) -> stores ----
    float* stg = (float*)(smem + SM_A);   // [64][132]
    {
        int r = w * 16 + (lane >> 2);
        int oc = (lane & 3) * 2;
        #pragma unroll
        for (int nt = 0; nt < 8; nt++) {
            int o = nt * 8 + oc;
            stg[o * 132 + r]            = acc[nt][0] + bsm[o];
            stg[(o + 1) * 132 + r]      = acc[nt][1] + bsm[o + 1];
            stg[o * 132 + r + 8]        = acc[nt][2] + bsm[o];
            stg[(o + 1) * 132 + r + 8]  = acc[nt][3] + bsm[o + 1];
        }
    }
    __syncthreads();
    for (int i = tid; i < 64 * 128; i += 256) {
        int o = i >> 7, mm = i & 127;
        int gm = m0 + mm;
        if (gm < M_)
            out[((size_t)(b * COUT + o) << 10) + 1 + gm] = stg[o * 132 + mm];
    }
}

// ---------------- kernel 4: zero column + optional index tail ------------
__global__ void tail_kernel(const void* __restrict__ idx_raw,
                            float* __restrict__ out, int mode) {
    int i = blockIdx.x * 256 + threadIdx.x;
    const int is64 = g_idx_is64;
    const int* i32 = (const int*)idx_raw;
    const long long* i64 = (const long long*)idx_raw;
    if (i < B_ * COUT) out[(size_t)i * OUTW] = 0.0f;
    if (i < B_ * M3) {
        long long v = is64 ? i64[i] : (long long)i32[i];
        if (mode == 1) {
            out[(size_t)B_ * COUT * OUTW + i] = (float)v;
        } else if (mode == 2) {
            ((long long*)out)[(size_t)(B_ * COUT * OUTW) / 2 + i] = v;
        }
    }
}

// -------------------------------------------------------------------------
extern "C" void kernel_launch(void* const* d_in, const int* in_sizes, int n_in,
                              void* d_out, int out_size) {
    const float* trees = nullptr;
    const void* indexes = nullptr;
    const float* W = nullptr;
    const float* bias = nullptr;
    for (int i = 0; i < n_in; i++) {
        switch (in_sizes[i]) {
            case B_ * CIN * NPTS: trees   = (const float*)d_in[i]; break;
            case B_ * M3:         indexes = d_in[i];               break;
            case COUT * CIN * 3:  W       = (const float*)d_in[i]; break;
            case COUT:            bias    = (const float*)d_in[i]; break;
        }
    }
    float* out = (float*)d_out;

    cudaFuncSetAttribute(convtree_mma_kernel,
                         cudaFuncAttributeMaxDynamicSharedMemorySize, SMEM_TOTAL);

    detect_kernel<<<1, 256>>>((const int*)indexes);
    transpose_split_kernel<<<dim3(NPTS / 32, CIN / 32, B_), dim3(32, 8)>>>(trees);
    wprep_kernel<<<(3 * 64 * 128 + 255) / 256, 256>>>(W);
    convtree_mma_kernel<<<dim3(8, B_), 256, SMEM_TOTAL>>>(indexes, bias, out);

    long long R = (long long)B_ * COUT * OUTW;
    long long I = (long long)B_ * M3;
    int mode = 0;
    if ((long long)out_size >= R + 2 * I)      mode = 2;
    else if ((long long)out_size >= R + I)     mode = 1;
    tail_kernel<<<(B_ * M3 + 255) / 256, 256>>>(indexes, out, mode);
}

// round 5
// speedup vs baseline: 2.4242x; 1.6119x over previous
#include <cuda_runtime.h>
#include <cuda_fp16.h>
#include <cstdint>

#define B_   256
#define CIN  128
#define NPTS 1024
#define M_   1023
#define COUT 64
#define M3   3069
#define OUTW 1024
#define NTILES 2048
#define GRID_P 148

// ---------------- scratch (__device__ globals) ----------------------------
__device__ __half g_th[(size_t)B_ * NPTS * CIN];          // [b][n][c] fp16
__device__ __align__(256) unsigned char g_Wsw[3 * 2 * 16384]; // W image hi/lo
__device__ int g_idx_is64;

// ---------------- PTX helpers ---------------------------------------------
__device__ __forceinline__ uint32_t smem_u32(const void* p) {
    uint32_t a;
    asm("{ .reg .u64 t; cvta.to.shared.u64 t, %1; cvt.u32.u64 %0, t; }"
        : "=r"(a) : "l"(p));
    return a;
}
#define CP_ASYNC16(dst, src) \
    asm volatile("cp.async.cg.shared.global [%0], [%1], 16;" :: "r"(dst), "l"(src) : "memory")
#define CP_COMMIT() asm volatile("cp.async.commit_group;" ::: "memory")
#define CP_WAIT0()  asm volatile("cp.async.wait_group 0;" ::: "memory")
#define CP_WAIT1()  asm volatile("cp.async.wait_group 1;" ::: "memory")
#define CP_WAIT2()  asm volatile("cp.async.wait_group 2;" ::: "memory")

#define LDSM_X4(r0, r1, r2, r3, addr) \
    asm volatile("ldmatrix.sync.aligned.m8n8.x4.shared.b16 {%0,%1,%2,%3}, [%4];" \
        : "=r"(r0), "=r"(r1), "=r"(r2), "=r"(r3) : "r"(addr))

#define MMA_F16(d, a, b0, b1) \
    asm volatile("mma.sync.aligned.m16n8k16.row.col.f32.f16.f16.f32 " \
        "{%0,%1,%2,%3}, {%4,%5,%6,%7}, {%8,%9}, {%0,%1,%2,%3};" \
        : "+f"((d)[0]), "+f"((d)[1]), "+f"((d)[2]), "+f"((d)[3]) \
        : "r"((a)[0]), "r"((a)[1]), "r"((a)[2]), "r"((a)[3]), "r"(b0), "r"(b1))

// ---------------- kernel 0: index dtype detection --------------------------
__global__ void detect_kernel(const int* __restrict__ idx32) {
    __shared__ int any_nz;
    if (threadIdx.x == 0) any_nz = 0;
    __syncthreads();
    int nz = 0;
    for (int i = threadIdx.x; i < 1024; i += blockDim.x)
        nz |= (idx32[2 * i + 1] != 0);
    if (nz) atomicOr(&any_nz, 1);
    __syncthreads();
    if (threadIdx.x == 0) g_idx_is64 = any_nz ? 0 : 1;
}

// ---------------- kernel 1: transpose + fp16 convert -----------------------
__global__ void transpose_half_kernel(const float* __restrict__ trees) {
    __shared__ float tile[32][33];
    int b = blockIdx.z;
    int nBase = blockIdx.x * 32;
    int cBase = blockIdx.y * 32;
    int tx = threadIdx.x, ty = threadIdx.y;
    const float* src = trees + (size_t)b * CIN * NPTS;
    #pragma unroll
    for (int i = 0; i < 4; i++)
        tile[ty + 8 * i][tx] = src[(size_t)(cBase + ty + 8 * i) * NPTS + nBase + tx];
    __syncthreads();
    #pragma unroll
    for (int i = 0; i < 4; i++) {
        int n = nBase + ty + 8 * i;
        g_th[(size_t)(b * NPTS + n) * CIN + cBase + tx] =
            __float2half(tile[tx][ty + 8 * i]);
    }
}

// ---------------- kernel 2: W -> fp16 hi/lo swizzled image -----------------
// byte layout: tap*32768 + mat*16384 + o*256 + swz(g,o)*16 + (c&7)*2
__global__ void wprep_kernel(const float* __restrict__ W) {
    int i = blockIdx.x * 256 + threadIdx.x;
    if (i >= 3 * 64 * 128) return;
    int c = i & 127;
    int o = (i >> 7) & 63;
    int k = i >> 13;
    float v = W[(o * CIN + c) * 3 + k];
    __half h = __float2half(v);
    __half l = __float2half(v - __half2float(h));
    int g = c >> 3;
    uint32_t swz = (g & 8) | ((g & 7) ^ (o & 7));
    uint32_t off = k * 32768 + o * 256 + (swz << 4) + (c & 7) * 2;
    *(__half*)(g_Wsw + off)         = h;    // mat 0 (hi)
    *(__half*)(g_Wsw + off + 16384) = l;    // mat 1 (lo)
}

// ---------------- kernel 3: persistent gather + HMMA fp16 GEMM -------------
// grid 148, 256 threads (8 warps, 4m x 2n; warp tile 32m x 32o).
// smem: W image 96KB | A ring 4 x 32KB (stage = one tap, 128 rows x 256B)
#define SM_W 0
#define SM_A 98304
#define SMEM_TOTAL 229376

__global__ void __launch_bounds__(256, 1) convtree_persist_kernel(
    const void* __restrict__ indexes_raw,
    const float* __restrict__ bias,
    float* __restrict__ out)
{
    extern __shared__ char smem[];
    const uint32_t sb = smem_u32(smem);
    const int tid  = threadIdx.x;
    const int lane = tid & 31;
    const int w    = tid >> 5;
    const int wm   = w & 3;        // m-group: rows wm*32 .. wm*32+31
    const int wn   = w >> 2;       // n-group: o wn*32 .. wn*32+31
    const int cta  = blockIdx.x;
    const int is64 = g_idx_is64;
    const int* i32 = (const int*)indexes_raw;
    const long long* i64 = (const long long*)indexes_raw;

    // ---- W image, loaded once per CTA (pre-swizzled, linear copy) ----
    for (int i = tid; i < 6144; i += 256)
        CP_ASYNC16(sb + SM_W + i * 16, (const char*)g_Wsw + i * 16);
    CP_COMMIT();                                     // commit c0

    // ---- per-thread bias values ----
    const int ocl = (lane & 3) * 2;
    float bv[2][2][2];
    #pragma unroll
    for (int ntp = 0; ntp < 2; ntp++)
        #pragma unroll
        for (int sub = 0; sub < 2; sub++) {
            int o = wn * 32 + ntp * 16 + sub * 8 + ocl;
            bv[ntp][sub][0] = bias[o];
            bv[ntp][sub][1] = bias[o + 1];
        }

    const int K = (NTILES - cta + GRID_P - 1) / GRID_P;  // tiles for this CTA
    const int S = 3 * K;                                  // stages (tile, tap)

    // stage loader: stage s = (local tile s/3, tap s%3) into ring slot s&3
    auto load_stage = [&](int s) {
        int j = s / 3, tap = s - 3 * j;
        int tile = cta + j * GRID_P;
        int b = tile >> 3, m0 = (tile & 7) << 7;
        int row = tid >> 1, half = tid & 1;
        int gm = m0 + row;
        int n = 0;
        if (gm < M_) {
            int flat = b * M3 + 3 * gm + tap;
            n = (is64 ? (int)i64[flat] : i32[flat]) & (NPTS - 1);
        }
        const char* src = (const char*)(g_th + ((size_t)(b * NPTS + n) << 7))
                          + half * 128;
        uint32_t dbase = sb + SM_A + ((s & 3) << 15) + row * 256;
        #pragma unroll
        for (int q = 0; q < 8; q++) {
            int g = half * 8 + q;
            uint32_t swz = (g & 8) | ((g & 7) ^ (row & 7));
            CP_ASYNC16(dbase + (swz << 4), src + q * 16);
        }
        CP_COMMIT();
    };

    // prologue: fill first 3 stages
    load_stage(0);
    load_stage(1);
    load_stage(2);

    float acc[2][2][2][4];   // [mt][ntp][sub][quad]
    #pragma unroll
    for (int a = 0; a < 2; a++)
        #pragma unroll
        for (int b2 = 0; b2 < 2; b2++)
            #pragma unroll
            for (int c = 0; c < 2; c++)
                #pragma unroll
                for (int d = 0; d < 4; d++) acc[a][b2][c][d] = 0.0f;

    const int ag = lane >> 4;
    const int bg = (lane >> 3) & 1;
    const int brow_base = wn * 32 + ((lane >> 4) << 3) + (lane & 7);
    const int l7 = lane & 7;

    for (int s = 0; s < S; s++) {
        if (s < S - 2) CP_WAIT2();
        else if (s == S - 2) CP_WAIT1();
        else CP_WAIT0();
        __syncthreads();                    // stage s visible; slot (s-1)&3 free

        if (s + 3 < S) load_stage(s + 3);   // prefetch into freed slot

        const int tap = s - 3 * (s / 3);
        const uint32_t abase = sb + SM_A + ((s & 3) << 15)
                             + (wm * 32 + (lane & 15)) * 256;
        const uint32_t wtap = sb + SM_W + tap * 32768;

        #pragma unroll
        for (int ks = 0; ks < 8; ks++) {
            const int g0 = ks * 2;
            uint32_t ah0[4], ah1[4];
            {
                int ga = g0 + ag;
                uint32_t swA = (uint32_t)((ga & 8) | ((ga & 7) ^ l7));
                LDSM_X4(ah0[0], ah0[1], ah0[2], ah0[3], abase + (swA << 4));
                LDSM_X4(ah1[0], ah1[1], ah1[2], ah1[3], abase + 4096 + (swA << 4));
            }
            int gb = g0 + bg;
            uint32_t swB = (uint32_t)((gb & 8) | ((gb & 7) ^ l7));
            #pragma unroll
            for (int mat = 0; mat < 2; mat++) {
                #pragma unroll
                for (int ntp = 0; ntp < 2; ntp++) {
                    uint32_t waddr = wtap + mat * 16384
                                   + (brow_base + ntp * 16) * 256 + (swB << 4);
                    uint32_t bh[4];
                    LDSM_X4(bh[0], bh[1], bh[2], bh[3], waddr);
                    MMA_F16(acc[0][ntp][0], ah0, bh[0], bh[1]);
                    MMA_F16(acc[0][ntp][1], ah0, bh[2], bh[3]);
                    MMA_F16(acc[1][ntp][0], ah1, bh[0], bh[1]);
                    MMA_F16(acc[1][ntp][1], ah1, bh[2], bh[3]);
                }
            }
        }

        // ---- epilogue after the 3rd tap of a tile: direct coalesced stores ----
        if (tap == 2) {
            int tile = cta + (s / 3) * GRID_P;
            int b = tile >> 3, m0 = (tile & 7) << 7;
            float* ob = out + (((size_t)b * COUT) << 10);
            int rl = lane >> 2;
            #pragma unroll
            for (int mt = 0; mt < 2; mt++) {
                int gmb = m0 + wm * 32 + mt * 16 + rl;
                #pragma unroll
                for (int ntp = 0; ntp < 2; ntp++) {
                    #pragma unroll
                    for (int sub = 0; sub < 2; sub++) {
                        int o = wn * 32 + ntp * 16 + sub * 8 + ocl;
                        float* p0 = ob + (((size_t)o) << 10) + 1;
                        float* p1 = ob + (((size_t)(o + 1)) << 10) + 1;
                        float* q = &acc[mt][ntp][sub][0];
                        if (gmb < M_) {
                            p0[gmb] = q[0] + bv[ntp][sub][0];
                            p1[gmb] = q[1] + bv[ntp][sub][1];
                        }
                        if (gmb + 8 < M_) {
                            p0[gmb + 8] = q[2] + bv[ntp][sub][0];
                            p1[gmb + 8] = q[3] + bv[ntp][sub][1];
                        }
                        q[0] = q[1] = q[2] = q[3] = 0.0f;
                    }
                }
            }
        }
    }
}

// ---------------- kernel 4: zero column + optional index tail --------------
__global__ void tail_kernel(const void* __restrict__ idx_raw,
                            float* __restrict__ out, int mode) {
    int i = blockIdx.x * 256 + threadIdx.x;
    const int is64 = g_idx_is64;
    const int* i32 = (const int*)idx_raw;
    const long long* i64 = (const long long*)idx_raw;
    if (i < B_ * COUT) out[(size_t)i * OUTW] = 0.0f;
    if (i < B_ * M3) {
        long long v = is64 ? i64[i] : (long long)i32[i];
        if (mode == 1) {
            out[(size_t)B_ * COUT * OUTW + i] = (float)v;
        } else if (mode == 2) {
            ((long long*)out)[(size_t)(B_ * COUT * OUTW) / 2 + i] = v;
        }
    }
}

// ---------------------------------------------------------------------------
extern "C" void kernel_launch(void* const* d_in, const int* in_sizes, int n_in,
                              void* d_out, int out_size) {
    const float* trees = nullptr;
    const void* indexes = nullptr;
    const float* W = nullptr;
    const float* bias = nullptr;
    for (int i = 0; i < n_in; i++) {
        switch (in_sizes[i]) {
            case B_ * CIN * NPTS: trees   = (const float*)d_in[i]; break;
            case B_ * M3:         indexes = d_in[i];               break;
            case COUT * CIN * 3:  W       = (const float*)d_in[i]; break;
            case COUT:            bias    = (const float*)d_in[i]; break;
        }
    }
    float* out = (float*)d_out;

    cudaFuncSetAttribute(convtree_persist_kernel,
                         cudaFuncAttributeMaxDynamicSharedMemorySize, SMEM_TOTAL);

    detect_kernel<<<1, 256>>>((const int*)indexes);
    transpose_half_kernel<<<dim3(NPTS / 32, CIN / 32, B_), dim3(32, 8)>>>(trees);
    wprep_kernel<<<(3 * 64 * 128 + 255) / 256, 256>>>(W);
    convtree_persist_kernel<<<GRID_P, 256, SMEM_TOTAL>>>(indexes, bias, out);

    long long R = (long long)B_ * COUT * OUTW;
    long long I = (long long)B_ * M3;
    int mode = 0;
    if ((long long)out_size >= R + 2 * I)      mode = 2;
    else if ((long long)out_size >= R + I)     mode = 1;
    tail_kernel<<<(B_ * M3 + 255) / 256, 256>>>(indexes, out, mode);
}

// round 6
// speedup vs baseline: 2.6859x; 1.1080x over previous
#include <cuda_runtime.h>
#include <cuda_fp16.h>
#include <cstdint>

#define B_   256
#define CIN  128
#define NPTS 1024
#define M_   1023
#define COUT 64
#define M3   3069
#define OUTW 1024
#define NTILES 2048
#define GRID_P 148

// ---------------- scratch (__device__ globals) ----------------------------
__device__ __half g_th[(size_t)B_ * NPTS * CIN];          // [b][n][c] fp16
__device__ __align__(256) unsigned char g_Wsw[3 * 2 * 16384]; // W image hi/lo
__device__ int g_idx_is64;

// ---------------- PTX helpers ---------------------------------------------
__device__ __forceinline__ uint32_t smem_u32(const void* p) {
    uint32_t a;
    asm("{ .reg .u64 t; cvta.to.shared.u64 t, %1; cvt.u32.u64 %0, t; }"
        : "=r"(a) : "l"(p));
    return a;
}
#define CP_ASYNC16(dst, src) \
    asm volatile("cp.async.cg.shared.global [%0], [%1], 16;" :: "r"(dst), "l"(src) : "memory")
#define CP_COMMIT() asm volatile("cp.async.commit_group;" ::: "memory")
#define CP_WAIT0()  asm volatile("cp.async.wait_group 0;" ::: "memory")
#define CP_WAIT1()  asm volatile("cp.async.wait_group 1;" ::: "memory")
#define CP_WAIT2()  asm volatile("cp.async.wait_group 2;" ::: "memory")

#define LDSM_X4(r0, r1, r2, r3, addr) \
    asm volatile("ldmatrix.sync.aligned.m8n8.x4.shared.b16 {%0,%1,%2,%3}, [%4];" \
        : "=r"(r0), "=r"(r1), "=r"(r2), "=r"(r3) : "r"(addr))

#define MMA_F16(d, a, b0, b1) \
    asm volatile("mma.sync.aligned.m16n8k16.row.col.f32.f16.f16.f32 " \
        "{%0,%1,%2,%3}, {%4,%5,%6,%7}, {%8,%9}, {%0,%1,%2,%3};" \
        : "+f"((d)[0]), "+f"((d)[1]), "+f"((d)[2]), "+f"((d)[3]) \
        : "r"((a)[0]), "r"((a)[1]), "r"((a)[2]), "r"((a)[3]), "r"(b0), "r"(b1))

// ---------------- kernel 0: index dtype detection --------------------------
__global__ void detect_kernel(const int* __restrict__ idx32) {
    __shared__ int any_nz;
    if (threadIdx.x == 0) any_nz = 0;
    __syncthreads();
    int nz = 0;
    for (int i = threadIdx.x; i < 1024; i += blockDim.x)
        nz |= (idx32[2 * i + 1] != 0);
    if (nz) atomicOr(&any_nz, 1);
    __syncthreads();
    if (threadIdx.x == 0) g_idx_is64 = any_nz ? 0 : 1;
}

// ---------------- kernel 1: transpose + fp16 convert -----------------------
__global__ void transpose_half_kernel(const float* __restrict__ trees) {
    __shared__ float tile[32][33];
    int b = blockIdx.z;
    int nBase = blockIdx.x * 32;
    int cBase = blockIdx.y * 32;
    int tx = threadIdx.x, ty = threadIdx.y;
    const float* src = trees + (size_t)b * CIN * NPTS;
    #pragma unroll
    for (int i = 0; i < 4; i++)
        tile[ty + 8 * i][tx] = src[(size_t)(cBase + ty + 8 * i) * NPTS + nBase + tx];
    __syncthreads();
    #pragma unroll
    for (int i = 0; i < 4; i++) {
        int n = nBase + ty + 8 * i;
        g_th[(size_t)(b * NPTS + n) * CIN + cBase + tx] =
            __float2half(tile[tx][ty + 8 * i]);
    }
}

// ---------------- kernel 2: W -> fp16 hi/lo swizzled image -----------------
// byte layout: tap*32768 + mat*16384 + o*256 + swz(g,o)*16 + (c&7)*2
__global__ void wprep_kernel(const float* __restrict__ W) {
    int i = blockIdx.x * 256 + threadIdx.x;
    if (i >= 3 * 64 * 128) return;
    int c = i & 127;
    int o = (i >> 7) & 63;
    int k = i >> 13;
    float v = W[(o * CIN + c) * 3 + k];
    __half h = __float2half(v);
    __half l = __float2half(v - __half2float(h));
    int g = c >> 3;
    uint32_t swz = (g & 8) | ((g & 7) ^ (o & 7));
    uint32_t off = k * 32768 + o * 256 + (swz << 4) + (c & 7) * 2;
    *(__half*)(g_Wsw + off)         = h;    // mat 0 (hi)
    *(__half*)(g_Wsw + off + 16384) = l;    // mat 1 (lo)
}

// ---------------- kernel 3: persistent gather + HMMA fp16 GEMM -------------
// grid 148, 512 threads (16 warps, 4m x 4n; warp tile 32m x 16o).
// smem: W image 96KB | A ring 4 x 32KB (stage = one tap, 128 rows x 256B)
#define SM_W 0
#define SM_A 98304
#define SMEM_TOTAL 229376

__global__ void __launch_bounds__(512, 1) convtree_persist_kernel(
    const void* __restrict__ indexes_raw,
    const float* __restrict__ bias,
    float* __restrict__ out)
{
    extern __shared__ char smem[];
    const uint32_t sb = smem_u32(smem);
    const int tid  = threadIdx.x;
    const int lane = tid & 31;
    const int w    = tid >> 5;
    const int wm   = w & 3;        // m-group: rows wm*32 .. wm*32+31
    const int wn   = w >> 2;       // n-group: o wn*16 .. wn*16+15
    const int cta  = blockIdx.x;
    const int is64 = g_idx_is64;
    const int* i32 = (const int*)indexes_raw;
    const long long* i64 = (const long long*)indexes_raw;

    // ---- W image, loaded once per CTA (pre-swizzled, linear copy) ----
    for (int i = tid; i < 6144; i += 512)
        CP_ASYNC16(sb + SM_W + i * 16, (const char*)g_Wsw + i * 16);
    CP_COMMIT();

    // ---- per-thread bias values ----
    const int ocl = (lane & 3) * 2;
    float bv[2][2];
    #pragma unroll
    for (int nt = 0; nt < 2; nt++) {
        int o = wn * 16 + nt * 8 + ocl;
        bv[nt][0] = bias[o];
        bv[nt][1] = bias[o + 1];
    }

    const int K = (NTILES - cta + GRID_P - 1) / GRID_P;  // tiles for this CTA
    const int S = 3 * K;                                  // stages (tile, tap)

    // stage loader: stage s = (local tile s/3, tap s%3) into ring slot s&3
    // 512 threads: 4 threads per m-row, 4 x 16B each
    auto load_stage = [&](int s) {
        int j = s / 3, tap = s - 3 * j;
        int tile = cta + j * GRID_P;
        int b = tile >> 3, m0 = (tile & 7) << 7;
        int row = tid >> 2, quarter = tid & 3;
        int gm = m0 + row;
        int n = 0;
        if (gm < M_) {
            int flat = b * M3 + 3 * gm + tap;
            n = (is64 ? (int)i64[flat] : i32[flat]) & (NPTS - 1);
        }
        const char* src = (const char*)(g_th + ((size_t)(b * NPTS + n) << 7))
                          + quarter * 64;
        uint32_t dbase = sb + SM_A + ((s & 3) << 15) + row * 256;
        #pragma unroll
        for (int q = 0; q < 4; q++) {
            int g = quarter * 4 + q;
            uint32_t swz = (g & 8) | ((g & 7) ^ (row & 7));
            CP_ASYNC16(dbase + (swz << 4), src + q * 16);
        }
        CP_COMMIT();
    };

    load_stage(0);
    load_stage(1);
    load_stage(2);

    float acc[2][2][4];   // [mt][nt][quad]
    #pragma unroll
    for (int a = 0; a < 2; a++)
        #pragma unroll
        for (int b2 = 0; b2 < 2; b2++)
            #pragma unroll
            for (int d = 0; d < 4; d++) acc[a][b2][d] = 0.0f;

    const int ag = lane >> 4;
    const int bg = (lane >> 3) & 1;
    const int brow = wn * 16 + ((lane >> 4) << 3) + (lane & 7);
    const int l7 = lane & 7;

    for (int s = 0; s < S; s++) {
        if (s < S - 2) CP_WAIT2();
        else if (s == S - 2) CP_WAIT1();
        else CP_WAIT0();
        __syncthreads();                    // stage s visible; slot (s-1)&3 free

        if (s + 3 < S) load_stage(s + 3);   // prefetch into freed slot

        const int tap = s - 3 * (s / 3);
        const uint32_t abase = sb + SM_A + ((s & 3) << 15)
                             + (wm * 32 + (lane & 15)) * 256;
        const uint32_t wrow = sb + SM_W + tap * 32768 + brow * 256;

        #pragma unroll
        for (int ks = 0; ks < 8; ks++) {
            const int g0 = ks * 2;
            uint32_t ah0[4], ah1[4];
            {
                int ga = g0 + ag;
                uint32_t swA = (uint32_t)((ga & 8) | ((ga & 7) ^ l7));
                LDSM_X4(ah0[0], ah0[1], ah0[2], ah0[3], abase + (swA << 4));
                LDSM_X4(ah1[0], ah1[1], ah1[2], ah1[3], abase + 4096 + (swA << 4));
            }
            int gb = g0 + bg;
            uint32_t swB = (uint32_t)((gb & 8) | ((gb & 7) ^ l7));
            #pragma unroll
            for (int mat = 0; mat < 2; mat++) {
                uint32_t bh[4];
                LDSM_X4(bh[0], bh[1], bh[2], bh[3],
                        wrow + mat * 16384 + (swB << 4));
                MMA_F16(acc[0][0], ah0, bh[0], bh[1]);
                MMA_F16(acc[0][1], ah0, bh[2], bh[3]);
                MMA_F16(acc[1][0], ah1, bh[0], bh[1]);
                MMA_F16(acc[1][1], ah1, bh[2], bh[3]);
            }
        }

        // ---- epilogue after the 3rd tap of a tile: direct coalesced stores ----
        if (tap == 2) {
            int tile = cta + (s / 3) * GRID_P;
            int b = tile >> 3, m0 = (tile & 7) << 7;
            float* ob = out + (((size_t)b * COUT) << 10);
            int rl = lane >> 2;
            #pragma unroll
            for (int mt = 0; mt < 2; mt++) {
                int gmb = m0 + wm * 32 + mt * 16 + rl;
                #pragma unroll
                for (int nt = 0; nt < 2; nt++) {
                    int o = wn * 16 + nt * 8 + ocl;
                    float* p0 = ob + (((size_t)o) << 10) + 1;
                    float* p1 = ob + (((size_t)(o + 1)) << 10) + 1;
                    float* q = &acc[mt][nt][0];
                    if (gmb < M_) {
                        p0[gmb] = q[0] + bv[nt][0];
                        p1[gmb] = q[1] + bv[nt][1];
                    }
                    if (gmb + 8 < M_) {
                        p0[gmb + 8] = q[2] + bv[nt][0];
                        p1[gmb + 8] = q[3] + bv[nt][1];
                    }
                    q[0] = q[1] = q[2] = q[3] = 0.0f;
                }
            }
        }
    }
}

// ---------------- kernel 4: zero column + optional index tail --------------
__global__ void tail_kernel(const void* __restrict__ idx_raw,
                            float* __restrict__ out, int mode) {
    int i = blockIdx.x * 256 + threadIdx.x;
    const int is64 = g_idx_is64;
    const int* i32 = (const int*)idx_raw;
    const long long* i64 = (const long long*)idx_raw;
    if (i < B_ * COUT) out[(size_t)i * OUTW] = 0.0f;
    if (i < B_ * M3) {
        long long v = is64 ? i64[i] : (long long)i32[i];
        if (mode == 1) {
            out[(size_t)B_ * COUT * OUTW + i] = (float)v;
        } else if (mode == 2) {
            ((long long*)out)[(size_t)(B_ * COUT * OUTW) / 2 + i] = v;
        }
    }
}

// ---------------------------------------------------------------------------
extern "C" void kernel_launch(void* const* d_in, const int* in_sizes, int n_in,
                              void* d_out, int out_size) {
    const float* trees = nullptr;
    const void* indexes = nullptr;
    const float* W = nullptr;
    const float* bias = nullptr;
    for (int i = 0; i < n_in; i++) {
        switch (in_sizes[i]) {
            case B_ * CIN * NPTS: trees   = (const float*)d_in[i]; break;
            case B_ * M3:         indexes = d_in[i];               break;
            case COUT * CIN * 3:  W       = (const float*)d_in[i]; break;
            case COUT:            bias    = (const float*)d_in[i]; break;
        }
    }
    float* out = (float*)d_out;

    cudaFuncSetAttribute(convtree_persist_kernel,
                         cudaFuncAttributeMaxDynamicSharedMemorySize, SMEM_TOTAL);

    detect_kernel<<<1, 256>>>((const int*)indexes);
    transpose_half_kernel<<<dim3(NPTS / 32, CIN / 32, B_), dim3(32, 8)>>>(trees);
    wprep_kernel<<<(3 * 64 * 128 + 255) / 256, 256>>>(W);
    convtree_persist_kernel<<<GRID_P, 512, SMEM_TOTAL>>>(indexes, bias, out);

    long long R = (long long)B_ * COUT * OUTW;
    long long I = (long long)B_ * M3;
    int mode = 0;
    if ((long long)out_size >= R + 2 * I)      mode = 2;
    else if ((long long)out_size >= R + I)     mode = 1;
    tail_kernel<<<(B_ * M3 + 255) / 256, 256>>>(indexes, out, mode);
}